// round 7
// baseline (speedup 1.0000x reference)
#include <cuda_runtime.h>
#include <float.h>
#include <math.h>

#define MAXROWS 8192
#define NT      256
#define NW      (NT / 32)
#define SLOTF4  12          // per-thread kept-float4 slots in smem (48 KB)

__device__ float g_rowloss[MAXROWS];

__device__ __forceinline__ float warpMax(float v) {
#pragma unroll
    for (int o = 16; o; o >>= 1) v = fmaxf(v, __shfl_xor_sync(0xffffffffu, v, o));
    return v;
}
__device__ __forceinline__ float warpReduceSum(float v) {
#pragma unroll
    for (int o = 16; o; o >>= 1) v += __shfl_down_sync(0xffffffffu, v, o);
    return v;
}
// Block sum returned to ALL threads (fixed-order partial sum -> deterministic, uniform).
__device__ __forceinline__ float blockReduceSumAll(float v, float* sbuf) {
    int lane = threadIdx.x & 31, warp = threadIdx.x >> 5;
    v = warpReduceSum(v);
    __syncthreads();
    if (lane == 0) sbuf[warp] = v;
    __syncthreads();
    float s = 0.f;
#pragma unroll
    for (int w = 0; w < NW; w++) s += sbuf[w];
    return s;
}

// Robust target load: auto-detect int32 vs int64 storage (int64 -> odd words zero).
__device__ __forceinline__ int load_target(const void* tgt, int row, int n, int d) {
    const int* t32 = (const int*)tgt;
    int lim = (n < 32) ? n : 32;
    bool is64 = true;
    for (int i = 0; i < lim; i++) is64 = is64 && (t32[2 * i + 1] == 0);
    long long v = is64 ? ((const long long*)tgt)[row] : (long long)t32[row];
    int t = (int)v;
    if (t < 0 || t >= d) t = 0;
    return t;
}

// Slow path helper: full-row sum of relu(0.5*x - tau)^2
__device__ __forceinline__ float relu2_pass(const float* xr, int d, float tau, float* sbuf) {
    float s = 0.f;
    for (int i = threadIdx.x; i < d; i += NT) {
        float t = fmaxf(fmaf(0.5f, __ldg(xr + i), -tau), 0.f);
        s = fmaf(t, t, s);
    }
    return blockReduceSumAll(s, sbuf);
}

#define M4(v) fmaxf(fmaxf((v).x, (v).y), fmaxf((v).z, (v).w))

__global__ __launch_bounds__(NT) void tsallis_kernel(const float* __restrict__ in,
                                                     const void* __restrict__ tgt,
                                                     int d, int n) {
    int row  = blockIdx.x;
    int tid  = threadIdx.x;
    int lane = tid & 31, warp = tid >> 5;
    const float* xr = in + (size_t)row * d;
    const float4* p4 = (const float4*)xr;

    __shared__ float4 kf4[SLOTF4][NT];   // kept-f4 buffer (thread-private columns)
    __shared__ float  swm[NW];
    __shared__ float  sred[NW];
    __shared__ int    sflag;

    if (tid == 0) sflag = 0;
    __syncthreads();

    int  nf4 = d >> 2;
    int  K   = nf4 / NT;                 // full rounds (31 for d=32000, NT=256)
    int  rem = nf4 - K * NT;
    bool shape_ok = ((d & 3) == 0) && (K >= 8) && (K <= 31);

    unsigned hit = 0;
    float rm = -FLT_MAX;                 // running max, raw input units

    if (shape_ok) {
        // ---- Warm-up: rounds 0..7, only per-f4 maxes retained in registers ----
        float m4a[8];
#pragma unroll
        for (int u = 0; u < 8; u++) {
            float4 v = p4[u * NT + tid];
            m4a[u] = M4(v);
        }
        {
            float cm = fmaxf(fmaxf(fmaxf(m4a[0], m4a[1]), fmaxf(m4a[2], m4a[3])),
                             fmaxf(fmaxf(m4a[4], m4a[5]), fmaxf(m4a[6], m4a[7])));
            rm = cm;
        }
        // ONE block max over the warm-up prefix (the only in-stream coordination)
        {
            float wv = warpMax(rm);
            if (lane == 0) swm[warp] = wv;
            __syncthreads();
        }
        float bm = swm[0];
#pragma unroll
        for (int w = 1; w < NW; w++) bm = fmaxf(bm, swm[w]);
        __syncthreads();                 // swm reused later
        float th = bm - 1.51f;           // raw units; covers X > maxX - 0.755

        // warm-up bits (from registers, retroactive full-prefix threshold)
#pragma unroll
        for (int u = 0; u < 8; u++)
            if (m4a[u] > th) hit |= (1u << u);

        // ---- Steady state: pure rowmax-shaped groups, zero coordination ----
        int k = 8;
        for (; k + 8 <= K; k += 8) {
            float m4[8];
#pragma unroll
            for (int u = 0; u < 8; u++) {
                float4 v = p4[(k + u) * NT + tid];
                m4[u] = M4(v);
            }
            float gm = fmaxf(fmaxf(fmaxf(m4[0], m4[1]), fmaxf(m4[2], m4[3])),
                             fmaxf(fmaxf(m4[4], m4[5]), fmaxf(m4[6], m4[7])));
#pragma unroll
            for (int u = 0; u < 8; u++)
                if (m4[u] > th) hit |= (1u << (k + u));   // stale th -> superset-safe
            rm = fmaxf(rm, gm);
            th = fmaxf(th, rm - 1.51f);
        }
        // leftover full rounds (<8, uniform count)
        if (k < K) {
            int lk = K - k;
            float m4[8];
#pragma unroll
            for (int u = 0; u < 8; u++) {
                if (u < lk) {
                    float4 v = p4[(k + u) * NT + tid];
                    m4[u] = M4(v);
                } else m4[u] = -FLT_MAX;
            }
            float gm = m4[0];
#pragma unroll
            for (int u = 1; u < 8; u++) gm = fmaxf(gm, m4[u]);
#pragma unroll
            for (int u = 0; u < 8; u++)
                if (u < lk && m4[u] > th) hit |= (1u << (k + u));
            rm = fmaxf(rm, gm);
            th = fmaxf(th, rm - 1.51f);
        }
        // remainder (ragged): bit K
        if (tid < rem) {
            float4 v = p4[K * NT + tid];
            float m4r = M4(v);
            rm = fmaxf(rm, m4r);
            if (m4r > th) hit |= (1u << K);
        }
    } else {
        float m = -FLT_MAX;
        for (int i = tid; i < d; i += NT) m = fmaxf(m, xr[i]);
        rm = m;
        atomicOr(&sflag, (tid == 0) ? 1 : 0);
    }

    // ---- Exact block max ----
    {
        float wv = warpMax(rm);
        __syncthreads();
        if (lane == 0) swm[warp] = wv;
        __syncthreads();
    }
    float bmax = swm[0];
#pragma unroll
    for (int w = 1; w < NW; w++) bmax = fmaxf(bmax, swm[w]);

    float maxX    = 0.5f * bmax;
    float tau_lo0 = maxX - 1.0f;
    float tau_hi0 = maxX - (float)(1.0 / sqrt((double)d));   // maxX - (1/d)^(alpha-1)
    float guard   = maxX - 0.754f;       // kept-set covers X > maxX - 0.755

    // ---- Gather hit f4s into smem (thread-private columns; mostly L2 hits) ----
    int cnt = 0;
    if (shape_ok) {
        unsigned hm = hit;
        while (hm) {
            int kb = __ffs(hm) - 1;
            hm &= hm - 1;
            if (cnt < SLOTF4) kf4[cnt][tid] = p4[kb * NT + tid];
            cnt++;
        }
        if (cnt > SLOTF4) atomicOr(&sflag, 1);
    }
    __syncthreads();
    bool slow = (sflag != 0);
    if (slow) cnt = 0;

    // ---- Fast bisection over kept f4s; mask = (f_m >= 0); guard every tau_m ----
    float dm     = tau_hi0 - tau_lo0;
    float tau_lo = tau_lo0;
    float tau_m  = tau_lo0;
    int   gtrip  = 0;
#pragma unroll 1
    for (int it = 0; it < 15; it++) {
        dm *= 0.5f;
        tau_m = tau_lo + dm;
        if (tau_m < guard) gtrip = 1;
        float s = 0.f;
        for (int j = 0; j < cnt; j++) {
            float4 v = kf4[j][tid];
            float t;
            t = fmaxf(fmaf(0.5f, v.x, -tau_m), 0.f); s = fmaf(t, t, s);
            t = fmaxf(fmaf(0.5f, v.y, -tau_m), 0.f); s = fmaf(t, t, s);
            t = fmaxf(fmaf(0.5f, v.z, -tau_m), 0.f); s = fmaf(t, t, s);
            t = fmaxf(fmaf(0.5f, v.w, -tau_m), 0.f); s = fmaf(t, t, s);
        }
        float fm = blockReduceSumAll(s, sred) - 1.0f;
        tau_lo = (fm >= 0.f) ? tau_m : tau_lo;    // uniform
    }

    bool slow2 = slow || (gtrip != 0);            // uniform across block
    float S3, PX, tau_f;

    if (!slow2) {
        tau_f = tau_m;
        float s3 = 0.f, px = 0.f;
        for (int j = 0; j < cnt; j++) {
            float4 v = kf4[j][tid];
            float X, t, p;
            X = 0.5f * v.x; t = fmaxf(X - tau_f, 0.f); p = t * t; s3 = fmaf(p, t, s3); px = fmaf(p, X, px);
            X = 0.5f * v.y; t = fmaxf(X - tau_f, 0.f); p = t * t; s3 = fmaf(p, t, s3); px = fmaf(p, X, px);
            X = 0.5f * v.z; t = fmaxf(X - tau_f, 0.f); p = t * t; s3 = fmaf(p, t, s3); px = fmaf(p, X, px);
            X = 0.5f * v.w; t = fmaxf(X - tau_f, 0.f); p = t * t; s3 = fmaf(p, t, s3); px = fmaf(p, X, px);
        }
        S3 = blockReduceSumAll(s3, sred);
        PX = blockReduceSumAll(px, sred);
    } else {
        // ---- Deterministic full-reference slow path (global reads) ----
        float tl = tau_lo0;
        float f_lo = relu2_pass(xr, d, tl, sred) - 1.0f;
        float dm2 = tau_hi0 - tl, tm = tl;
#pragma unroll 1
        for (int it = 0; it < 15; it++) {
            dm2 *= 0.5f;
            tm = tl + dm2;
            float fm = relu2_pass(xr, d, tm, sred) - 1.0f;
            tl = (fm * f_lo >= 0.f) ? tm : tl;
        }
        tau_f = tm;
        float s3 = 0.f, px = 0.f;
        for (int i = tid; i < d; i += NT) {
            float X = 0.5f * __ldg(xr + i);
            float t = fmaxf(X - tau_f, 0.f);
            float p = t * t;
            s3 = fmaf(p, t, s3);
            px = fmaf(p, X, px);
        }
        S3 = blockReduceSumAll(s3, sred);
        PX = blockReduceSumAll(px, sred);
    }

    if (tid == 0) {
        int t = load_target(tgt, row, n, d);
        float xt = __ldg(xr + t);
        // loss = (1 - S3)/(alpha*(alpha-1)) + sum(p*input) - input[target]
        //      = (1 - S3)/0.75 + 2*PX - xt        (input = 2*X)
        g_rowloss[row] = (1.0f - S3) / 0.75f + 2.0f * PX - xt;
    }
}

// Deterministic mean over rows
__global__ __launch_bounds__(1024) void reduce_kernel(float* __restrict__ out, int n) {
    __shared__ float sbuf[32];
    float s = 0.f;
    int n4 = n >> 2;
    const float4* p4 = (const float4*)g_rowloss;
    for (int i = threadIdx.x; i < n4; i += 1024) {
        float4 v = p4[i];
        s += (v.x + v.y) + (v.z + v.w);
    }
    for (int i = (n4 << 2) + threadIdx.x; i < n; i += 1024) s += g_rowloss[i];
    s = warpReduceSum(s);
    if ((threadIdx.x & 31) == 0) sbuf[threadIdx.x >> 5] = s;
    __syncthreads();
    if (threadIdx.x < 32) {
        float x = sbuf[threadIdx.x];
        x = warpReduceSum(x);
        if (threadIdx.x == 0) out[0] = x / (float)n;
    }
}

extern "C" void kernel_launch(void* const* d_in, const int* in_sizes, int n_in,
                              void* d_out, int out_size) {
    // Pick logits vs targets by size: the big buffer is the [n, d] logits.
    int idx_in = 0, idx_tg = 1;
    if (n_in >= 2 && in_sizes[1] > in_sizes[0]) { idx_in = 1; idx_tg = 0; }
    const float* in  = (const float*)d_in[idx_in];
    const void*  tgt = d_in[idx_tg];

    int n = in_sizes[idx_tg];
    if (n <= 0) n = 1;
    int d = in_sizes[idx_in] / n;
    if (n > MAXROWS) n = MAXROWS;   // shapes fixed: 4096 x 32000

    tsallis_kernel<<<n, NT>>>(in, tgt, d, n);
    reduce_kernel<<<1, 1024>>>((float*)d_out, n);
}